// round 1
// baseline (speedup 1.0000x reference)
#include <cuda_runtime.h>
#include <math_constants.h>

// Problem constants
#define BB 128
#define TT 2048
#define HH 256
#define NW 32                     // warps per CTA
#define ROWS_PER_WARP (TT / NW)   // 64
#define OUTD 128

// Fully fused attention:
//   v_b = W_score @ h_t[b]                      (tiny)
//   s_t = <hidden[b,t,:], v_b>                  (streamed)
//   softmax over t  -- ONLINE, fused with:
//   ctx = sum_t w_t * hidden[b,t,:]             (same single pass over hidden)
//   out = tanh(concat(ctx, h_t) @ W_att)        (tiny)
// Single 256MB read of hidden_states -> HBM-bound, ~37us floor.
__global__ __launch_bounds__(1024, 1)
void attn_fused_kernel(const float* __restrict__ hidden,
                       const float* __restrict__ Wscore,
                       const float* __restrict__ Watt,
                       float* __restrict__ out)
{
    __shared__ float s_ht[HH];            // h_t for this batch
    __shared__ float s_v[HH];             // v = W_score @ h_t
    __shared__ float s_wm[NW];            // per-warp running max
    __shared__ float s_wz[NW];            // per-warp Z
    __shared__ float s_acc[NW][HH];       // per-warp weighted accumulators (32KB)
    __shared__ float s_e[NW];             // per-warp exp(m_w - M)
    __shared__ float s_Zt;                // global normalizer
    __shared__ float s_pre[2 * HH];       // concat(ctx, h_t)

    const int b    = blockIdx.x;
    const int tid  = threadIdx.x;
    const int w    = tid >> 5;
    const int lane = tid & 31;
    const float* hb = hidden + (size_t)b * TT * HH;

    // ---- load h_t = hidden[b, T-1, :] ----
    if (tid < HH) s_ht[tid] = hb[(size_t)(TT - 1) * HH + tid];
    __syncthreads();

    // ---- v[h] = sum_k W_score[h,k] * h_t[k]; warp w covers h = 8w..8w+7,
    //      lanes stride k (coalesced row reads) ----
    #pragma unroll
    for (int j = 0; j < 8; j++) {
        const int h = w * 8 + j;
        const float* row = Wscore + h * HH;
        float p = 0.f;
        #pragma unroll
        for (int k = lane; k < HH; k += 32) p += row[k] * s_ht[k];
        #pragma unroll
        for (int off = 16; off; off >>= 1) p += __shfl_xor_sync(0xffffffffu, p, off);
        if (lane == 0) s_v[h] = p;
    }
    __syncthreads();

    // ---- register-resident v slice for this lane (elements 8*lane .. 8*lane+7) ----
    const float4 v0 = *(const float4*)(s_v + lane * 8);
    const float4 v1 = *(const float4*)(s_v + lane * 8 + 4);

    // ---- streamed pass: score + online-softmax-weighted accumulation ----
    float  m = -CUDART_INF_F;
    float  Z = 0.f;
    float4 a0 = make_float4(0.f, 0.f, 0.f, 0.f);
    float4 a1 = make_float4(0.f, 0.f, 0.f, 0.f);

    const float* rowp = hb + (size_t)(w * ROWS_PER_WARP) * HH + lane * 8;
    #pragma unroll 4
    for (int i = 0; i < ROWS_PER_WARP; i++) {
        const float4 x0 = *(const float4*)(rowp);
        const float4 x1 = *(const float4*)(rowp + 4);
        rowp += HH;

        float s = x0.x * v0.x + x0.y * v0.y + x0.z * v0.z + x0.w * v0.w
                + x1.x * v1.x + x1.y * v1.y + x1.z * v1.z + x1.w * v1.w;
        #pragma unroll
        for (int off = 16; off; off >>= 1) s += __shfl_xor_sync(0xffffffffu, s, off);
        // s is warp-uniform now -> branch is warp-uniform (cheap, rarely taken)
        if (s > m) {
            const float sc = __expf(m - s);   // first iter: exp(-inf) = 0, zeroes state
            Z *= sc;
            a0.x *= sc; a0.y *= sc; a0.z *= sc; a0.w *= sc;
            a1.x *= sc; a1.y *= sc; a1.z *= sc; a1.w *= sc;
            m = s;
        }
        const float p = __expf(s - m);
        Z += p;
        a0.x += p * x0.x; a0.y += p * x0.y; a0.z += p * x0.z; a0.w += p * x0.w;
        a1.x += p * x1.x; a1.y += p * x1.y; a1.z += p * x1.z; a1.w += p * x1.w;
    }

    // ---- publish per-warp partials ----
    if (lane == 0) { s_wm[w] = m; s_wz[w] = Z; }
    *(float4*)(&s_acc[w][lane * 8])     = a0;
    *(float4*)(&s_acc[w][lane * 8 + 4]) = a1;
    __syncthreads();

    // ---- warp 0: global max + normalizer ----
    if (w == 0) {
        const float mw = s_wm[lane];
        float M = mw;
        #pragma unroll
        for (int off = 16; off; off >>= 1) M = fmaxf(M, __shfl_xor_sync(0xffffffffu, M, off));
        const float e = __expf(mw - M);
        s_e[lane] = e;
        float z = e * s_wz[lane];
        #pragma unroll
        for (int off = 16; off; off >>= 1) z += __shfl_xor_sync(0xffffffffu, z, off);
        if (lane == 0) s_Zt = z;
    }
    __syncthreads();

    // ---- combine accumulators -> context; build pre = concat(ctx, h_t) ----
    if (tid < HH) {
        float c = 0.f;
        #pragma unroll
        for (int ww = 0; ww < NW; ww++) c += s_e[ww] * s_acc[ww][tid];
        c /= s_Zt;
        s_pre[tid]      = c;
        s_pre[HH + tid] = s_ht[tid];
    }
    __syncthreads();

    // ---- out[b, j] = tanh( sum_i pre[i] * W_att[i, j] ), j in [0,128) ----
    if (tid < OUTD) {
        float acc = 0.f;
        #pragma unroll 8
        for (int i = 0; i < 2 * HH; i++)
            acc += s_pre[i] * Watt[i * OUTD + tid];
        out[b * OUTD + tid] = tanhf(acc);
    }
}

extern "C" void kernel_launch(void* const* d_in, const int* in_sizes, int n_in,
                              void* d_out, int out_size) {
    const float* hidden = (const float*)d_in[0];   // (128, 2048, 256) f32
    const float* Wscore = (const float*)d_in[1];   // (256, 256) f32
    const float* Watt   = (const float*)d_in[2];   // (512, 128) f32
    float* out = (float*)d_out;                    // (128, 128) f32
    attn_fused_kernel<<<BB, 1024>>>(hidden, Wscore, Watt, out);
}